// round 16
// baseline (speedup 1.0000x reference)
#include <cuda_runtime.h>
#include <cuda_fp16.h>
#include <cstdint>

#define BB 2
#define SS 2048
#define EE 1024
#define HH 16
#define MM (BB*SS)          // 4096
#define OUT_ELEMS (MM*EE)   // 4194304
#define NT (SS/64)          // 32 k-tiles

// ---------------- scratch (device globals, all fp16) ----------------
__device__ __half g_x16[(size_t)MM*EE];
__device__ __half g_Wq16[EE*EE], g_Wk16[EE*EE], g_Wv16[EE*EE], g_Wo16[EE*EE];
__device__ __half g_Q16[(size_t)MM*EE];   // [b,h,s,d], pre-scaled by gate*0.125*log2e
__device__ __half g_K16[(size_t)MM*EE];   // [b,h,s,d]
__device__ __half g_Vt [(size_t)MM*EE];   // [b,h,d,s]
__device__ __half g_C16[(size_t)MM*EE];   // ctx [b,s,e]

// ---------------- asm helpers ----------------
__device__ __forceinline__ void mma_f16(float (&d)[4], const uint32_t (&a)[4],
                                        const uint32_t* b) {
    asm volatile(
        "mma.sync.aligned.m16n8k16.row.col.f32.f16.f16.f32 "
        "{%0,%1,%2,%3}, {%4,%5,%6,%7}, {%8,%9}, {%0,%1,%2,%3};\n"
        : "+f"(d[0]), "+f"(d[1]), "+f"(d[2]), "+f"(d[3])
        : "r"(a[0]), "r"(a[1]), "r"(a[2]), "r"(a[3]), "r"(b[0]), "r"(b[1]));
}
__device__ __forceinline__ void ldsm4(uint32_t (&r)[4], const void* p) {
    uint32_t a = (uint32_t)__cvta_generic_to_shared(p);
    asm volatile("ldmatrix.sync.aligned.m8n8.x4.shared.b16 {%0,%1,%2,%3}, [%4];\n"
                 : "=r"(r[0]), "=r"(r[1]), "=r"(r[2]), "=r"(r[3]) : "r"(a));
}
__device__ __forceinline__ void cpa16(void* d, const void* s) {
    uint32_t a = (uint32_t)__cvta_generic_to_shared(d);
    asm volatile("cp.async.cg.shared.global [%0], [%1], 16;\n" :: "r"(a), "l"(s));
}
__device__ __forceinline__ float ex2(float x) {
    float r;
    asm("ex2.approx.ftz.f32 %0, %1;" : "=f"(r) : "f"(x));
    return r;
}
#define CP_COMMIT() asm volatile("cp.async.commit_group;\n")
#define CP_WAIT(N)  asm volatile("cp.async.wait_group %0;\n" :: "n"(N))

// ---------------- prep: fp32 -> fp16 (x + 4 weights, one launch) ----------------
__global__ void cvt_all(const float* __restrict__ sx, const float* __restrict__ s0,
                        const float* __restrict__ s1, const float* __restrict__ s2,
                        const float* __restrict__ s3,
                        __half* __restrict__ dx, __half* __restrict__ d0,
                        __half* __restrict__ d1, __half* __restrict__ d2,
                        __half* __restrict__ d3) {
    int i = blockIdx.x * blockDim.x + threadIdx.x;
    const float* s; __half* d; int n4;
    switch (blockIdx.y) {
        case 0: s = sx; d = dx; n4 = MM*EE/4; break;
        case 1: s = s0; d = d0; n4 = EE*EE/4; break;
        case 2: s = s1; d = d1; n4 = EE*EE/4; break;
        case 3: s = s2; d = d2; n4 = EE*EE/4; break;
        default: s = s3; d = d3; n4 = EE*EE/4; break;
    }
    if (i >= n4) return;
    float4 v = ((const float4*)s)[i];
    ((__half2*)d)[i*2]   = __floats2half2_rn(v.x, v.y);
    ((__half2*)d)[i*2+1] = __floats2half2_rn(v.z, v.w);
}

// ---------------------------------------------------------------------------
// fp16 GEMM core: BM=128 BN=128 BK=64, 256 thr, 2-stage ring (R12 structure).
// ---------------------------------------------------------------------------
#define GST 72              // 64 + 8 pad (halves)
#define GARR (128 * GST)    // one array (A or B): 9216 halves = 18432 B
#define GSTG (2 * GARR)     // one stage (A + B)

// shared mainloop: fills acc for (m0, n0) with A @ B^T
__device__ __forceinline__ void gemm_mainloop(
    const __half* __restrict__ A, const __half* __restrict__ B,
    __half* smh, int m0, int n0, float (&acc)[2][8][4])
{
    const int tid = threadIdx.x, lane = tid & 31, wid = tid >> 5;
    const int wm = wid & 3, wn = wid >> 2;
    const int arow = (lane & 7) + ((lane >> 3) & 1) * 8, acol = ((lane >> 4) & 1) * 8;
    const int brow = (lane & 7) + ((lane >> 4) & 1) * 8, bcol = ((lane >> 3) & 1) * 8;

    auto issue = [&](int k0, int buf) {
        __half* base = smh + buf * GSTG;
#pragma unroll
        for (int i = 0; i < 8; i++) {
            int idx = tid + i * 256;          // 0..2047
            int isB = idx >= 1024;
            int rem = idx & 1023;
            int row = rem >> 3, ch = rem & 7;
            const __half* src = (isB ? B + (size_t)(n0 + row) * EE
                                     : A + (size_t)(m0 + row) * EE) + k0 + ch * 8;
            cpa16(base + isB * GARR + row * GST + ch * 8, src);
        }
    };

    issue(0, 0);  CP_COMMIT();
    issue(64, 1); CP_COMMIT();

    for (int s = 0; s < EE / 64; s++) {
        CP_WAIT(1);
        __syncthreads();
        __half* sA = smh + (s & 1) * GSTG;
        __half* sB = sA + GARR;

#pragma unroll
        for (int ks = 0; ks < 64; ks += 16) {
            uint32_t a[2][4];
#pragma unroll
            for (int mt = 0; mt < 2; mt++)
                ldsm4(a[mt], sA + (wm * 32 + mt * 16 + arow) * GST + ks + acol);
#pragma unroll
            for (int np = 0; np < 4; np++) {
                uint32_t bf[4];
                ldsm4(bf, sB + (wn * 64 + np * 16 + brow) * GST + ks + bcol);
#pragma unroll
                for (int mt = 0; mt < 2; mt++) {
                    mma_f16(acc[mt][np*2],   a[mt], bf);
                    mma_f16(acc[mt][np*2+1], a[mt], bf + 2);
                }
            }
        }
        __syncthreads();
        if (s + 2 < EE / 64) issue((s + 2) * 64, s & 1);
        CP_COMMIT();
    }
    CP_WAIT(0);
}

// merged Q/K/V projection: blockIdx.z = 0(Q) / 1(K) / 2(V)
__global__ __launch_bounds__(256, 2) void gemm_qkv(
    const __half* __restrict__ A,
    const __half* __restrict__ Wq, const __half* __restrict__ Wk,
    const __half* __restrict__ Wv,
    const float* __restrict__ bq, const float* __restrict__ bk,
    const float* __restrict__ bv,
    const float* __restrict__ z,
    __half* __restrict__ Q, __half* __restrict__ K, __half* __restrict__ V)
{
    extern __shared__ __half smh[];
    const int zsel = blockIdx.z;
    const __half* B = (zsel == 0) ? Wq : (zsel == 1) ? Wk : Wv;
    const float* bias = (zsel == 0) ? bq : (zsel == 1) ? bk : bv;
    const int m0 = blockIdx.y * 128, n0 = blockIdx.x * 128;

    float acc[2][8][4] = {};
    gemm_mainloop(A, B, smh, m0, n0, acc);

    const int tid = threadIdx.x, lane = tid & 31, wid = tid >> 5;
    const int wm = wid & 3, wn = wid >> 2;

#pragma unroll
    for (int mt = 0; mt < 2; mt++) {
        int r = m0 + wm * 32 + mt * 16 + (lane >> 2);
        int b_ = r >> 11, s_ = r & 2047;
#pragma unroll
        for (int nt = 0; nt < 8; nt++) {
            int c = n0 + wn * 64 + nt * 8 + 2 * (lane & 3);
            float b0 = bias[c], b1 = bias[c + 1];
            float v00 = acc[mt][nt][0] + b0, v01 = acc[mt][nt][1] + b1;
            float v10 = acc[mt][nt][2] + b0, v11 = acc[mt][nt][3] + b1;
            int hh = c >> 6, dd = c & 63;
            if (zsel == 2) {       // V transposed [b,h,d,s]
                size_t o0 = (((size_t)b_ * HH + hh) * 64 + dd) * SS + s_;
                V[o0]          = __float2half(v00);
                V[o0 + SS]     = __float2half(v01);
                V[o0 + 8]      = __float2half(v10);
                V[o0 + SS + 8] = __float2half(v11);
            } else {
                if (zsel == 0) {
                    float mult = 0.18033688f / (1.f + __expf(-z[hh]));
                    v00 *= mult; v01 *= mult; v10 *= mult; v11 *= mult;
                }
                __half* Oh = (zsel == 0) ? Q : K;
                size_t o0 = (((size_t)b_ * HH + hh) * SS + s_) * 64 + dd;
                *(__half2*)&Oh[o0] = __floats2half2_rn(v00, v01);
                *(__half2*)&Oh[o0 + (size_t)8 * 64] = __floats2half2_rn(v10, v11);
            }
        }
    }
}

// O projection -> fp32 [m,n]
__global__ __launch_bounds__(256, 2) void gemm_out(
    const __half* __restrict__ A, const __half* __restrict__ B,
    const float* __restrict__ bias, float* __restrict__ O)
{
    extern __shared__ __half smh[];
    const int m0 = blockIdx.y * 128, n0 = blockIdx.x * 128;

    float acc[2][8][4] = {};
    gemm_mainloop(A, B, smh, m0, n0, acc);

    const int tid = threadIdx.x, lane = tid & 31, wid = tid >> 5;
    const int wm = wid & 3, wn = wid >> 2;

#pragma unroll
    for (int mt = 0; mt < 2; mt++) {
        int r = m0 + wm * 32 + mt * 16 + (lane >> 2);
#pragma unroll
        for (int nt = 0; nt < 8; nt++) {
            int c = n0 + wn * 64 + nt * 8 + 2 * (lane & 3);
            float b0 = bias[c], b1 = bias[c + 1];
            *(float2*)&O[(size_t)r * EE + c] =
                make_float2(acc[mt][nt][0] + b0, acc[mt][nt][1] + b1);
            *(float2*)&O[(size_t)(r + 8) * EE + c] =
                make_float2(acc[mt][nt][2] + b0, acc[mt][nt][3] + b1);
        }
    }
}

// ---------------------------------------------------------------------------
// Attention (unchanged from R8): fp16, per (b,h,64-query tile), 128 thr.
// Q pre-scaled so p = 2^s. Row sums via ones-column MMA.
// ---------------------------------------------------------------------------
#define AST 72

__global__ __launch_bounds__(128, 4) void attn_pipe(
    const __half* __restrict__ Q16, const __half* __restrict__ K16,
    const __half* __restrict__ Vt_, __half* __restrict__ C16)
{
    extern __shared__ __half smf[];
    __half* sQ = smf;                       // 64*72
    __half* sK = sQ + 64 * AST;             // 2 x 64*72
    __half* sV = sK + 2 * 64 * AST;         // 2 x 64*72

    const int tid = threadIdx.x, lane = tid & 31, w = tid >> 5;
    const int q0 = blockIdx.x * 64, h = blockIdx.y, b = blockIdx.z;
    const int bh = b * HH + h;

    const size_t qkBase = (size_t)bh * SS * 64;   // [bh][s][d]
    const size_t vBase  = (size_t)bh * 64 * SS;   // [bh][d][s]

    const int arow = (lane & 7) + ((lane >> 3) & 1) * 8, acol = ((lane >> 4) & 1) * 8;
    const int brow = (lane & 7) + ((lane >> 4) & 1) * 8, bcol = ((lane >> 3) & 1) * 8;

    auto issue = [&](int kt, int buf) {
#pragma unroll
        for (int i = 0; i < 8; i++) {
            int idx = tid + i * 128;           // 0..1023
            if (idx < 512) {                   // K tile
                int row = idx >> 3, ch = idx & 7;
                cpa16(sK + buf * 64 * AST + row * AST + ch * 8,
                      K16 + qkBase + (size_t)(kt * 64 + row) * 64 + ch * 8);
            } else {                           // V tile
                int rem = idx - 512, row = rem >> 3, ch = rem & 7;
                cpa16(sV + buf * 64 * AST + row * AST + ch * 8,
                      Vt_ + vBase + (size_t)row * SS + kt * 64 + ch * 8);
            }
        }
    };

#pragma unroll
    for (int i = 0; i < 4; i++) {
        int idx = tid + i * 128;               // 0..511
        int row = idx >> 3, ch = idx & 7;
        cpa16(sQ + row * AST + ch * 8,
              Q16 + qkBase + (size_t)(q0 + row) * 64 + ch * 8);
    }
    issue(0, 0); CP_COMMIT();
    issue(1, 1); CP_COMMIT();

    CP_WAIT(1);
    __syncthreads();

    uint32_t q[4][4];
#pragma unroll
    for (int kc = 0; kc < 4; kc++)
        ldsm4(q[kc], sQ + (w * 16 + arow) * AST + kc * 16 + acol);

    float o[8][4] = {};
    float ol[4] = {};                       // row-sum accumulator (ones column)
    const uint32_t ONE2 = 0x3C003C00u;      // half2(1,1)
    const uint32_t ones[2] = {ONE2, ONE2};

    for (int kt = 0; kt < NT; kt++) {
        int buf = kt & 1;
        if (kt) { CP_WAIT(1); __syncthreads(); }

        const __half* k0p = sK + buf * 64 * AST;
        const __half* v0p = sV + buf * 64 * AST;

        // S = Q K^T (already log2-scaled)
        float s[8][4] = {};
#pragma unroll
        for (int nc = 0; nc < 4; nc++) {
#pragma unroll
            for (int kc = 0; kc < 4; kc++) {
                uint32_t kb[4];
                ldsm4(kb, k0p + (nc * 16 + brow) * AST + kc * 16 + bcol);
                mma_f16(s[nc*2],   q[kc], kb);
                mma_f16(s[nc*2+1], q[kc], kb + 2);
            }
        }

        // p = 2^s, packed fp16 A-frags (C-frag == A-frag identity)
        uint32_t p[4][4];
#pragma unroll
        for (int t = 0; t < 8; t++) {
            float e0 = ex2(s[t][0]), e1 = ex2(s[t][1]);
            float e2 = ex2(s[t][2]), e3 = ex2(s[t][3]);
            int kc = t >> 1, hf = t & 1;
            __half2 p01 = __floats2half2_rn(e0, e1);
            __half2 p23 = __floats2half2_rn(e2, e3);
            p[kc][hf*2]   = *(uint32_t*)&p01;
            p[kc][hf*2+1] = *(uint32_t*)&p23;
        }

        // O += P V ; row sums += P @ ones
#pragma unroll
        for (int kc = 0; kc < 4; kc++) {
#pragma unroll
            for (int nd = 0; nd < 4; nd++) {
                uint32_t vb[4];
                ldsm4(vb, v0p + (nd * 16 + brow) * AST + kc * 16 + bcol);
                mma_f16(o[nd*2],   p[kc], vb);
                mma_f16(o[nd*2+1], p[kc], vb + 2);
            }
            mma_f16(ol, p[kc], ones);
        }

        __syncthreads();
        if (kt + 2 < NT) issue(kt + 2, buf);
        CP_COMMIT();
    }
    CP_WAIT(0);

    float inv0 = 1.f / ol[0], inv1 = 1.f / ol[2];

    int r0 = q0 + w * 16 + (lane >> 2);
#pragma unroll
    for (int t = 0; t < 8; t++) {
        int c = h * 64 + t * 8 + 2 * (lane & 3);
        size_t g0 = ((size_t)b * SS + r0) * EE + c;
        size_t g1 = ((size_t)b * SS + r0 + 8) * EE + c;
        *(__half2*)&C16[g0] = __floats2half2_rn(o[t][0] * inv0, o[t][1] * inv0);
        *(__half2*)&C16[g1] = __floats2half2_rn(o[t][2] * inv1, o[t][3] * inv1);
    }
}

// Penalty = 0.01 * sum(sigmoid(z))
__global__ void penalty_kernel(const float* __restrict__ z,
                               float* __restrict__ out, int out_size)
{
    if (out_size <= OUT_ELEMS) return;
    float v = 0.f;
    if (threadIdx.x < HH) v = 1.f / (1.f + expf(-z[threadIdx.x]));
#pragma unroll
    for (int off = 16; off > 0; off >>= 1)
        v += __shfl_xor_sync(0xffffffffu, v, off);
    if (threadIdx.x == 0) out[OUT_ELEMS] = v * 0.01f;
}

extern "C" void kernel_launch(void* const* d_in, const int* in_sizes, int n_in,
                              void* d_out, int out_size)
{
    const float* x  = (const float*)d_in[0];
    const float* Wq = (const float*)d_in[1];
    const float* bq = (const float*)d_in[2];
    const float* Wk = (const float*)d_in[3];
    const float* bk = (const float*)d_in[4];
    const float* Wv = (const float*)d_in[5];
    const float* bv = (const float*)d_in[6];
    const float* Wo = (const float*)d_in[7];
    const float* bo = (const float*)d_in[8];
    const float* z  = (const float*)d_in[9];
    float* out = (float*)d_out;

    __half *x16, *Wq16, *Wk16, *Wv16, *Wo16, *Q16, *K16, *Vt, *C16;
    cudaGetSymbolAddress((void**)&x16, g_x16);
    cudaGetSymbolAddress((void**)&Wq16, g_Wq16);
    cudaGetSymbolAddress((void**)&Wk16, g_Wk16);
    cudaGetSymbolAddress((void**)&Wv16, g_Wv16);
    cudaGetSymbolAddress((void**)&Wo16, g_Wo16);
    cudaGetSymbolAddress((void**)&Q16, g_Q16);
    cudaGetSymbolAddress((void**)&K16, g_K16);
    cudaGetSymbolAddress((void**)&Vt, g_Vt);
    cudaGetSymbolAddress((void**)&C16, g_C16);

    // prep: one launch (x + 4 weights)
    dim3 pgrid((MM*EE/4 + 255)/256, 5);
    cvt_all<<<pgrid, 256>>>(x, Wq, Wk, Wv, Wo, x16, Wq16, Wk16, Wv16, Wo16);

    const int FSM = 2 * GSTG * 2;         // 73728 B
    cudaFuncSetAttribute(gemm_qkv, cudaFuncAttributeMaxDynamicSharedMemorySize, FSM);
    cudaFuncSetAttribute(gemm_out, cudaFuncAttributeMaxDynamicSharedMemorySize, FSM);
    // max-shared carveout: lets attn fit 4 CTAs/SM (4 x 46KB = 184KB > default)
    cudaFuncSetAttribute(gemm_qkv, cudaFuncAttributePreferredSharedMemoryCarveout,
                         cudaSharedmemCarveoutMaxShared);
    cudaFuncSetAttribute(gemm_out, cudaFuncAttributePreferredSharedMemoryCarveout,
                         cudaSharedmemCarveoutMaxShared);

    // merged QKV: 768 CTAs in one launch
    dim3 qkvgrid(EE / 128, MM / 128, 3);  // (8, 32, 3)
    gemm_qkv<<<qkvgrid, 256, FSM>>>(x16, Wq16, Wk16, Wv16, bq, bk, bv, z,
                                    Q16, K16, Vt);

    const int ASM = 5 * 64 * AST * 2;     // 46080 B
    cudaFuncSetAttribute(attn_pipe, cudaFuncAttributeMaxDynamicSharedMemorySize, ASM);
    cudaFuncSetAttribute(attn_pipe, cudaFuncAttributePreferredSharedMemoryCarveout,
                         cudaSharedmemCarveoutMaxShared);
    dim3 agrid(SS / 64, HH, BB);          // (32, 16, 2)
    attn_pipe<<<agrid, 128, ASM>>>(Q16, K16, Vt, C16);

    dim3 ggrid(EE / 128, MM / 128);       // (8, 32)
    gemm_out<<<ggrid, 256, FSM>>>(C16, Wo16, bo, out);

    penalty_kernel<<<1, 32>>>(z, out, out_size);
}

// round 17
// speedup vs baseline: 1.5399x; 1.5399x over previous
#include <cuda_runtime.h>
#include <cuda_fp16.h>
#include <cstdint>

#define BB 2
#define SS 2048
#define EE 1024
#define HH 16
#define MM (BB*SS)          // 4096
#define OUT_ELEMS (MM*EE)   // 4194304
#define NT (SS/64)          // 32 k-tiles

// ---------------- scratch (device globals, all fp16) ----------------
__device__ __half g_x16[(size_t)MM*EE];
__device__ __half g_Wq16[EE*EE], g_Wk16[EE*EE], g_Wv16[EE*EE], g_Wo16[EE*EE];
__device__ __half g_Q16[(size_t)MM*EE];   // [b,h,s,d], pre-scaled by gate*0.125*log2e
__device__ __half g_K16[(size_t)MM*EE];   // [b,h,s,d]
__device__ __half g_Vt [(size_t)MM*EE];   // [b,h,d,s]
__device__ __half g_C16[(size_t)MM*EE];   // ctx [b,s,e]

// ---------------- asm helpers ----------------
__device__ __forceinline__ void mma_f16(float (&d)[4], const uint32_t (&a)[4],
                                        const uint32_t* b) {
    asm volatile(
        "mma.sync.aligned.m16n8k16.row.col.f32.f16.f16.f32 "
        "{%0,%1,%2,%3}, {%4,%5,%6,%7}, {%8,%9}, {%0,%1,%2,%3};\n"
        : "+f"(d[0]), "+f"(d[1]), "+f"(d[2]), "+f"(d[3])
        : "r"(a[0]), "r"(a[1]), "r"(a[2]), "r"(a[3]), "r"(b[0]), "r"(b[1]));
}
__device__ __forceinline__ void ldsm4(uint32_t (&r)[4], const void* p) {
    uint32_t a = (uint32_t)__cvta_generic_to_shared(p);
    asm volatile("ldmatrix.sync.aligned.m8n8.x4.shared.b16 {%0,%1,%2,%3}, [%4];\n"
                 : "=r"(r[0]), "=r"(r[1]), "=r"(r[2]), "=r"(r[3]) : "r"(a));
}
__device__ __forceinline__ void cpa16(void* d, const void* s) {
    uint32_t a = (uint32_t)__cvta_generic_to_shared(d);
    asm volatile("cp.async.cg.shared.global [%0], [%1], 16;\n" :: "r"(a), "l"(s));
}
__device__ __forceinline__ float ex2(float x) {
    float r;
    asm("ex2.approx.ftz.f32 %0, %1;" : "=f"(r) : "f"(x));
    return r;
}
#define CP_COMMIT() asm volatile("cp.async.commit_group;\n")
#define CP_WAIT(N)  asm volatile("cp.async.wait_group %0;\n" :: "n"(N))

// ---------------- prep: fp32 -> fp16 (x + 4 weights, one launch) ----------------
__global__ void cvt_all(const float* __restrict__ sx, const float* __restrict__ s0,
                        const float* __restrict__ s1, const float* __restrict__ s2,
                        const float* __restrict__ s3,
                        __half* __restrict__ dx, __half* __restrict__ d0,
                        __half* __restrict__ d1, __half* __restrict__ d2,
                        __half* __restrict__ d3) {
    int i = blockIdx.x * blockDim.x + threadIdx.x;
    const float* s; __half* d; int n4;
    switch (blockIdx.y) {
        case 0: s = sx; d = dx; n4 = MM*EE/4; break;
        case 1: s = s0; d = d0; n4 = EE*EE/4; break;
        case 2: s = s1; d = d1; n4 = EE*EE/4; break;
        case 3: s = s2; d = d2; n4 = EE*EE/4; break;
        default: s = s3; d = d3; n4 = EE*EE/4; break;
    }
    if (i >= n4) return;
    float4 v = ((const float4*)s)[i];
    ((__half2*)d)[i*2]   = __floats2half2_rn(v.x, v.y);
    ((__half2*)d)[i*2+1] = __floats2half2_rn(v.z, v.w);
}

// ---------------------------------------------------------------------------
// fp16 GEMM core: BM=128 BN=128 BK=64, 256 thr, 2-stage ring (R12 structure).
// ---------------------------------------------------------------------------
#define GST 72              // 64 + 8 pad (halves)
#define GARR (128 * GST)    // one array (A or B): 9216 halves = 18432 B
#define GSTG (2 * GARR)     // one stage (A + B)

// shared mainloop: fills acc for (m0, n0) with A @ B^T
__device__ __forceinline__ void gemm_mainloop(
    const __half* __restrict__ A, const __half* __restrict__ B,
    __half* smh, int m0, int n0, float (&acc)[2][8][4])
{
    const int tid = threadIdx.x, lane = tid & 31, wid = tid >> 5;
    const int wm = wid & 3, wn = wid >> 2;
    const int arow = (lane & 7) + ((lane >> 3) & 1) * 8, acol = ((lane >> 4) & 1) * 8;
    const int brow = (lane & 7) + ((lane >> 4) & 1) * 8, bcol = ((lane >> 3) & 1) * 8;

    auto issue = [&](int k0, int buf) {
        __half* base = smh + buf * GSTG;
#pragma unroll
        for (int i = 0; i < 8; i++) {
            int idx = tid + i * 256;          // 0..2047
            int isB = idx >= 1024;
            int rem = idx & 1023;
            int row = rem >> 3, ch = rem & 7;
            const __half* src = (isB ? B + (size_t)(n0 + row) * EE
                                     : A + (size_t)(m0 + row) * EE) + k0 + ch * 8;
            cpa16(base + isB * GARR + row * GST + ch * 8, src);
        }
    };

    issue(0, 0);  CP_COMMIT();
    issue(64, 1); CP_COMMIT();

    for (int s = 0; s < EE / 64; s++) {
        CP_WAIT(1);
        __syncthreads();
        __half* sA = smh + (s & 1) * GSTG;
        __half* sB = sA + GARR;

#pragma unroll
        for (int ks = 0; ks < 64; ks += 16) {
            uint32_t a[2][4];
#pragma unroll
            for (int mt = 0; mt < 2; mt++)
                ldsm4(a[mt], sA + (wm * 32 + mt * 16 + arow) * GST + ks + acol);
#pragma unroll
            for (int np = 0; np < 4; np++) {
                uint32_t bf[4];
                ldsm4(bf, sB + (wn * 64 + np * 16 + brow) * GST + ks + bcol);
#pragma unroll
                for (int mt = 0; mt < 2; mt++) {
                    mma_f16(acc[mt][np*2],   a[mt], bf);
                    mma_f16(acc[mt][np*2+1], a[mt], bf + 2);
                }
            }
        }
        __syncthreads();
        if (s + 2 < EE / 64) issue((s + 2) * 64, s & 1);
        CP_COMMIT();
    }
    CP_WAIT(0);
}

// merged Q/K/V projection: blockIdx.z = 0(Q) / 1(K) / 2(V)
__global__ __launch_bounds__(256, 2) void gemm_qkv(
    const __half* __restrict__ A,
    const __half* __restrict__ Wq, const __half* __restrict__ Wk,
    const __half* __restrict__ Wv,
    const float* __restrict__ bq, const float* __restrict__ bk,
    const float* __restrict__ bv,
    const float* __restrict__ z,
    __half* __restrict__ Q, __half* __restrict__ K, __half* __restrict__ V)
{
    extern __shared__ __half smh[];
    const int zsel = blockIdx.z;
    const __half* B = (zsel == 0) ? Wq : (zsel == 1) ? Wk : Wv;
    const float* bias = (zsel == 0) ? bq : (zsel == 1) ? bk : bv;
    const int m0 = blockIdx.y * 128, n0 = blockIdx.x * 128;

    float acc[2][8][4] = {};
    gemm_mainloop(A, B, smh, m0, n0, acc);

    const int tid = threadIdx.x, lane = tid & 31, wid = tid >> 5;
    const int wm = wid & 3, wn = wid >> 2;

#pragma unroll
    for (int mt = 0; mt < 2; mt++) {
        int r = m0 + wm * 32 + mt * 16 + (lane >> 2);
        int b_ = r >> 11, s_ = r & 2047;
#pragma unroll
        for (int nt = 0; nt < 8; nt++) {
            int c = n0 + wn * 64 + nt * 8 + 2 * (lane & 3);
            float b0 = bias[c], b1 = bias[c + 1];
            float v00 = acc[mt][nt][0] + b0, v01 = acc[mt][nt][1] + b1;
            float v10 = acc[mt][nt][2] + b0, v11 = acc[mt][nt][3] + b1;
            int hh = c >> 6, dd = c & 63;
            if (zsel == 2) {       // V transposed [b,h,d,s]
                size_t o0 = (((size_t)b_ * HH + hh) * 64 + dd) * SS + s_;
                V[o0]          = __float2half(v00);
                V[o0 + SS]     = __float2half(v01);
                V[o0 + 8]      = __float2half(v10);
                V[o0 + SS + 8] = __float2half(v11);
            } else {
                if (zsel == 0) {
                    float mult = 0.18033688f / (1.f + __expf(-z[hh]));
                    v00 *= mult; v01 *= mult; v10 *= mult; v11 *= mult;
                }
                __half* Oh = (zsel == 0) ? Q : K;
                size_t o0 = (((size_t)b_ * HH + hh) * SS + s_) * 64 + dd;
                *(__half2*)&Oh[o0] = __floats2half2_rn(v00, v01);
                *(__half2*)&Oh[o0 + (size_t)8 * 64] = __floats2half2_rn(v10, v11);
            }
        }
    }
}

// O projection -> fp32 [m,n]
__global__ __launch_bounds__(256, 2) void gemm_out(
    const __half* __restrict__ A, const __half* __restrict__ B,
    const float* __restrict__ bias, float* __restrict__ O)
{
    extern __shared__ __half smh[];
    const int m0 = blockIdx.y * 128, n0 = blockIdx.x * 128;

    float acc[2][8][4] = {};
    gemm_mainloop(A, B, smh, m0, n0, acc);

    const int tid = threadIdx.x, lane = tid & 31, wid = tid >> 5;
    const int wm = wid & 3, wn = wid >> 2;

#pragma unroll
    for (int mt = 0; mt < 2; mt++) {
        int r = m0 + wm * 32 + mt * 16 + (lane >> 2);
#pragma unroll
        for (int nt = 0; nt < 8; nt++) {
            int c = n0 + wn * 64 + nt * 8 + 2 * (lane & 3);
            float b0 = bias[c], b1 = bias[c + 1];
            *(float2*)&O[(size_t)r * EE + c] =
                make_float2(acc[mt][nt][0] + b0, acc[mt][nt][1] + b1);
            *(float2*)&O[(size_t)(r + 8) * EE + c] =
                make_float2(acc[mt][nt][2] + b0, acc[mt][nt][3] + b1);
        }
    }
}

// ---------------------------------------------------------------------------
// Attention (unchanged from R8): fp16, per (b,h,64-query tile), 128 thr.
// Q pre-scaled so p = 2^s. Row sums via ones-column MMA.
// ---------------------------------------------------------------------------
#define AST 72

__global__ __launch_bounds__(128, 4) void attn_pipe(
    const __half* __restrict__ Q16, const __half* __restrict__ K16,
    const __half* __restrict__ Vt_, __half* __restrict__ C16)
{
    extern __shared__ __half smf[];
    __half* sQ = smf;                       // 64*72
    __half* sK = sQ + 64 * AST;             // 2 x 64*72
    __half* sV = sK + 2 * 64 * AST;         // 2 x 64*72

    const int tid = threadIdx.x, lane = tid & 31, w = tid >> 5;
    const int q0 = blockIdx.x * 64, h = blockIdx.y, b = blockIdx.z;
    const int bh = b * HH + h;

    const size_t qkBase = (size_t)bh * SS * 64;   // [bh][s][d]
    const size_t vBase  = (size_t)bh * 64 * SS;   // [bh][d][s]

    const int arow = (lane & 7) + ((lane >> 3) & 1) * 8, acol = ((lane >> 4) & 1) * 8;
    const int brow = (lane & 7) + ((lane >> 4) & 1) * 8, bcol = ((lane >> 3) & 1) * 8;

    auto issue = [&](int kt, int buf) {
#pragma unroll
        for (int i = 0; i < 8; i++) {
            int idx = tid + i * 128;           // 0..1023
            if (idx < 512) {                   // K tile
                int row = idx >> 3, ch = idx & 7;
                cpa16(sK + buf * 64 * AST + row * AST + ch * 8,
                      K16 + qkBase + (size_t)(kt * 64 + row) * 64 + ch * 8);
            } else {                           // V tile
                int rem = idx - 512, row = rem >> 3, ch = rem & 7;
                cpa16(sV + buf * 64 * AST + row * AST + ch * 8,
                      Vt_ + vBase + (size_t)row * SS + kt * 64 + ch * 8);
            }
        }
    };

#pragma unroll
    for (int i = 0; i < 4; i++) {
        int idx = tid + i * 128;               // 0..511
        int row = idx >> 3, ch = idx & 7;
        cpa16(sQ + row * AST + ch * 8,
              Q16 + qkBase + (size_t)(q0 + row) * 64 + ch * 8);
    }
    issue(0, 0); CP_COMMIT();
    issue(1, 1); CP_COMMIT();

    CP_WAIT(1);
    __syncthreads();

    uint32_t q[4][4];
#pragma unroll
    for (int kc = 0; kc < 4; kc++)
        ldsm4(q[kc], sQ + (w * 16 + arow) * AST + kc * 16 + acol);

    float o[8][4] = {};
    float ol[4] = {};                       // row-sum accumulator (ones column)
    const uint32_t ONE2 = 0x3C003C00u;      // half2(1,1)
    const uint32_t ones[2] = {ONE2, ONE2};

    for (int kt = 0; kt < NT; kt++) {
        int buf = kt & 1;
        if (kt) { CP_WAIT(1); __syncthreads(); }

        const __half* k0p = sK + buf * 64 * AST;
        const __half* v0p = sV + buf * 64 * AST;

        // S = Q K^T (already log2-scaled)
        float s[8][4] = {};
#pragma unroll
        for (int nc = 0; nc < 4; nc++) {
#pragma unroll
            for (int kc = 0; kc < 4; kc++) {
                uint32_t kb[4];
                ldsm4(kb, k0p + (nc * 16 + brow) * AST + kc * 16 + bcol);
                mma_f16(s[nc*2],   q[kc], kb);
                mma_f16(s[nc*2+1], q[kc], kb + 2);
            }
        }

        // p = 2^s, packed fp16 A-frags (C-frag == A-frag identity)
        uint32_t p[4][4];
#pragma unroll
        for (int t = 0; t < 8; t++) {
            float e0 = ex2(s[t][0]), e1 = ex2(s[t][1]);
            float e2 = ex2(s[t][2]), e3 = ex2(s[t][3]);
            int kc = t >> 1, hf = t & 1;
            __half2 p01 = __floats2half2_rn(e0, e1);
            __half2 p23 = __floats2half2_rn(e2, e3);
            p[kc][hf*2]   = *(uint32_t*)&p01;
            p[kc][hf*2+1] = *(uint32_t*)&p23;
        }

        // O += P V ; row sums += P @ ones
#pragma unroll
        for (int kc = 0; kc < 4; kc++) {
#pragma unroll
            for (int nd = 0; nd < 4; nd++) {
                uint32_t vb[4];
                ldsm4(vb, v0p + (nd * 16 + brow) * AST + kc * 16 + bcol);
                mma_f16(o[nd*2],   p[kc], vb);
                mma_f16(o[nd*2+1], p[kc], vb + 2);
            }
            mma_f16(ol, p[kc], ones);
        }

        __syncthreads();
        if (kt + 2 < NT) issue(kt + 2, buf);
        CP_COMMIT();
    }
    CP_WAIT(0);

    float inv0 = 1.f / ol[0], inv1 = 1.f / ol[2];

    int r0 = q0 + w * 16 + (lane >> 2);
#pragma unroll
    for (int t = 0; t < 8; t++) {
        int c = h * 64 + t * 8 + 2 * (lane & 3);
        size_t g0 = ((size_t)b * SS + r0) * EE + c;
        size_t g1 = ((size_t)b * SS + r0 + 8) * EE + c;
        *(__half2*)&C16[g0] = __floats2half2_rn(o[t][0] * inv0, o[t][1] * inv0);
        *(__half2*)&C16[g1] = __floats2half2_rn(o[t][2] * inv1, o[t][3] * inv1);
    }
}

// Penalty = 0.01 * sum(sigmoid(z))
__global__ void penalty_kernel(const float* __restrict__ z,
                               float* __restrict__ out, int out_size)
{
    if (out_size <= OUT_ELEMS) return;
    float v = 0.f;
    if (threadIdx.x < HH) v = 1.f / (1.f + expf(-z[threadIdx.x]));
#pragma unroll
    for (int off = 16; off > 0; off >>= 1)
        v += __shfl_xor_sync(0xffffffffu, v, off);
    if (threadIdx.x == 0) out[OUT_ELEMS] = v * 0.01f;
}

extern "C" void kernel_launch(void* const* d_in, const int* in_sizes, int n_in,
                              void* d_out, int out_size)
{
    const float* x  = (const float*)d_in[0];
    const float* Wq = (const float*)d_in[1];
    const float* bq = (const float*)d_in[2];
    const float* Wk = (const float*)d_in[3];
    const float* bk = (const float*)d_in[4];
    const float* Wv = (const float*)d_in[5];
    const float* bv = (const float*)d_in[6];
    const float* Wo = (const float*)d_in[7];
    const float* bo = (const float*)d_in[8];
    const float* z  = (const float*)d_in[9];
    float* out = (float*)d_out;

    __half *x16, *Wq16, *Wk16, *Wv16, *Wo16, *Q16, *K16, *Vt, *C16;
    cudaGetSymbolAddress((void**)&x16, g_x16);
    cudaGetSymbolAddress((void**)&Wq16, g_Wq16);
    cudaGetSymbolAddress((void**)&Wk16, g_Wk16);
    cudaGetSymbolAddress((void**)&Wv16, g_Wv16);
    cudaGetSymbolAddress((void**)&Wo16, g_Wo16);
    cudaGetSymbolAddress((void**)&Q16, g_Q16);
    cudaGetSymbolAddress((void**)&K16, g_K16);
    cudaGetSymbolAddress((void**)&Vt, g_Vt);
    cudaGetSymbolAddress((void**)&C16, g_C16);

    // prep: one launch (x + 4 weights)
    dim3 pgrid((MM*EE/4 + 255)/256, 5);
    cvt_all<<<pgrid, 256>>>(x, Wq, Wk, Wv, Wo, x16, Wq16, Wk16, Wv16, Wo16);

    const int FSM = 2 * GSTG * 2;         // 73728 B
    cudaFuncSetAttribute(gemm_qkv, cudaFuncAttributeMaxDynamicSharedMemorySize, FSM);
    cudaFuncSetAttribute(gemm_out, cudaFuncAttributeMaxDynamicSharedMemorySize, FSM);

    // merged QKV: 768 CTAs in one launch
    dim3 qkvgrid(EE / 128, MM / 128, 3);  // (8, 32, 3)
    gemm_qkv<<<qkvgrid, 256, FSM>>>(x16, Wq16, Wk16, Wv16, bq, bk, bv, z,
                                    Q16, K16, Vt);

    const int ASM = 5 * 64 * AST * 2;     // 46080 B
    cudaFuncSetAttribute(attn_pipe, cudaFuncAttributeMaxDynamicSharedMemorySize, ASM);
    dim3 agrid(SS / 64, HH, BB);          // (32, 16, 2)
    attn_pipe<<<agrid, 128, ASM>>>(Q16, K16, Vt, C16);

    dim3 ggrid(EE / 128, MM / 128);       // (8, 32)
    gemm_out<<<ggrid, 256, FSM>>>(C16, Wo16, bo, out);

    penalty_kernel<<<1, 32>>>(z, out, out_size);
}